// round 13
// baseline (speedup 1.0000x reference)
#include <cuda_runtime.h>

#define NB 8
#define NH 8
#define NS 1024
#define NE 64

// Scratch (allocation-free rule: __device__ globals)
// layout: g_qkv[(b*NH+h)*NS + s] -> 2 float4: {q0',q1',q2',k0} {k1,k2,v0,v1}
// q' is pre-scaled by (1/8)*log2(e) so score exp becomes a single ex2.
__device__ float4 g_qkv[NB * NH * NS * 2];
// layout: g_o16[(b*NS+s)*8 + h] = (out0, out1) for head h
__device__ float2 g_o16[NB * NS * 8];

// ---------------------------------------------------------------------------
// Kernel 1: angles -> cosines -> prefix products -> q/k/v
// thread g: h fastest -> fully coalesced float4 reads of x
// ---------------------------------------------------------------------------
__global__ void __launch_bounds__(256) qkv_kernel(const float* __restrict__ x,
                                                  const float* __restrict__ theta) {
    int g = blockIdx.x * blockDim.x + threadIdx.x;   // 0..65535
    int h = g & 7;
    int s = (g >> 3) & (NS - 1);
    int b = g >> 13;

    const float4* xp = reinterpret_cast<const float4*>(x + ((b * NS + s) * NE + h * 8));
    float4 x0 = xp[0];
    float4 x1 = xp[1];
    float4 t0 = reinterpret_cast<const float4*>(theta)[0];
    float4 t1 = reinterpret_cast<const float4*>(theta)[1];

    float c0 = cosf(x0.x + t0.x);
    float c1 = cosf(x0.y + t0.y);
    float c2 = cosf(x0.z + t0.z);
    float c3 = cosf(x0.w + t0.w);
    float c4 = cosf(x1.x + t1.x);
    float c5 = cosf(x1.y + t1.y);
    float c6 = cosf(x1.z + t1.z);
    float c7 = cosf(x1.w + t1.w);

    // meas[w] = c0*...*cw (w>=1), meas[0] = c1*...*c7
    float m1 = c0 * c1;
    float m2 = m1 * c2;
    float m3 = m2 * c3;
    float m4 = m3 * c4;
    float m5 = m4 * c5;
    float m6 = m5 * c6;
    float m7 = m6 * c7;
    float m0 = c1 * c2;
    m0 *= c3; m0 *= c4; m0 *= c5; m0 *= c6; m0 *= c7;

    // q pre-scaled: score = (q.k)/8; exp(score) = exp2( (q*QS).k )
    const float QS = 0.125f * 1.4426950408889634f;

    float4* qp = &g_qkv[((b * NH + h) * NS + s) * 2];
    qp[0] = make_float4(m0 * QS, m1 * QS, m2 * QS, m3);
    qp[1] = make_float4(m4, m5, m6, m7);
}

// ---------------------------------------------------------------------------
// Kernel 2: attention. One block = one (b,h) pair x one tile of 256 query rows.
// K/V for the whole sequence live in smem; inner loop is warp-uniform so
// every LDS is a broadcast (no bank conflicts). Scores in [-0.375,0.375]:
// plain exp (no max subtraction) is exact softmax up to normalization.
// ---------------------------------------------------------------------------
#define TILES 4
#define ATTN_THREADS 128

__global__ void __launch_bounds__(ATTN_THREADS) attn_kernel() {
    __shared__ float4 kv4[NS];   // (k0,k1,k2,v0)
    __shared__ float  v1s[NS];   // v1

    int bh   = blockIdx.x / TILES;
    int tile = blockIdx.x % TILES;
    const float4* base = &g_qkv[bh * NS * 2];

    for (int t = threadIdx.x; t < NS; t += ATTN_THREADS) {
        float4 f1 = base[2 * t];
        float4 f2 = base[2 * t + 1];
        kv4[t] = make_float4(f1.w, f2.x, f2.y, f2.z);
        v1s[t] = f2.w;
    }

    int row0 = tile * (NS / TILES) + threadIdx.x;   // 2 rows per thread
    int row1 = row0 + ATTN_THREADS;
    float4 qa = base[2 * row0];
    float4 qb = base[2 * row1];
    __syncthreads();

    float sum0 = 0.f, a00 = 0.f, a01 = 0.f;
    float sum1 = 0.f, a10 = 0.f, a11 = 0.f;

#pragma unroll 8
    for (int t = 0; t < NS; ++t) {
        float4 kv = kv4[t];
        float  v1 = v1s[t];
        float d0 = fmaf(qa.x, kv.x, fmaf(qa.y, kv.y, qa.z * kv.z));
        float d1 = fmaf(qb.x, kv.x, fmaf(qb.y, kv.y, qb.z * kv.z));
        float e0, e1;
        asm("ex2.approx.f32 %0, %1;" : "=f"(e0) : "f"(d0));
        asm("ex2.approx.f32 %0, %1;" : "=f"(e1) : "f"(d1));
        sum0 += e0; a00 = fmaf(e0, kv.w, a00); a01 = fmaf(e0, v1, a01);
        sum1 += e1; a10 = fmaf(e1, kv.w, a10); a11 = fmaf(e1, v1, a11);
    }

    int b = bh >> 3;
    int h = bh & 7;
    float inv0 = __fdividef(1.f, sum0);
    float inv1 = __fdividef(1.f, sum1);
    g_o16[(b * NS + row0) * 8 + h] = make_float2(a00 * inv0, a01 * inv0);
    g_o16[(b * NS + row1) * 8 + h] = make_float2(a10 * inv1, a11 * inv1);
}

// ---------------------------------------------------------------------------
// Kernel 3: combine. y[tok,e] = sum_f o16[tok,f]*W[e,f] + bias[e]
// W in smem padded to stride 17 (kills the 16-way bank conflict of stride 16).
// One block handles 32 tokens.
// ---------------------------------------------------------------------------
__global__ void __launch_bounds__(256) combine_kernel(const float* __restrict__ W,
                                                      const float* __restrict__ bias,
                                                      float* __restrict__ out) {
    __shared__ float Ws[64 * 17];
    __shared__ float bs[64];
    __shared__ float os[32 * 16];

    int tid = threadIdx.x;
    for (int i = tid; i < 64 * 16; i += 256)
        Ws[(i >> 4) * 17 + (i & 15)] = W[i];
    if (tid < 64) bs[tid] = bias[tid];

    int tokbase = blockIdx.x * 32;
    const float* o16 = reinterpret_cast<const float*>(g_o16);
    for (int i = tid; i < 32 * 16; i += 256)
        os[i] = o16[tokbase * 16 + i];
    __syncthreads();

    for (int idx = tid; idx < 32 * 64; idx += 256) {
        int tok = idx >> 6;
        int e   = idx & 63;
        float acc = bs[e];
        const float* wrow = &Ws[e * 17];
        const float* orow = &os[tok * 16];
#pragma unroll
        for (int f = 0; f < 16; ++f)
            acc = fmaf(orow[f], wrow[f], acc);
        out[(tokbase + tok) * 64 + e] = acc;
    }
}

// ---------------------------------------------------------------------------
extern "C" void kernel_launch(void* const* d_in, const int* in_sizes, int n_in,
                              void* d_out, int out_size) {
    const float* x     = (const float*)d_in[0];   // (8,1024,64)
    const float* theta = (const float*)d_in[1];   // (8,)
    const float* W     = (const float*)d_in[2];   // (64,16)
    const float* bias  = (const float*)d_in[3];   // (64,)
    float* out = (float*)d_out;                   // (8,1024,64)

    qkv_kernel<<<NB * NH * NS / 256, 256>>>(x, theta);
    attn_kernel<<<NB * NH * TILES, ATTN_THREADS>>>();
    combine_kernel<<<NB * NS / 32, 256>>>(W, bias, out);
}

// round 14
// speedup vs baseline: 1.0398x; 1.0398x over previous
#include <cuda_runtime.h>

#define NB 8
#define NH 8
#define NS 1024
#define NE 64

// Scratch (allocation-free rule: __device__ globals)
// layout: g_qkv[(b*NH+h)*NS + s] -> 2 float4: {q0',q1',q2',k0} {k1,k2,v0,v1}
// q' is pre-scaled by (1/8)*log2(e) so score exp becomes a single ex2.
__device__ float4 g_qkv[NB * NH * NS * 2];
// layout: g_o16[(b*NS+s)*8 + h] = (out0, out1) for head h
__device__ float2 g_o16[NB * NS * 8];

// ---------------------------------------------------------------------------
// Kernel 1: angles -> cosines -> prefix products -> q/k/v
// thread g: h fastest -> fully coalesced float4 reads of x
// ---------------------------------------------------------------------------
__global__ void __launch_bounds__(256) qkv_kernel(const float* __restrict__ x,
                                                  const float* __restrict__ theta) {
    int g = blockIdx.x * blockDim.x + threadIdx.x;   // 0..65535
    int h = g & 7;
    int s = (g >> 3) & (NS - 1);
    int b = g >> 13;

    const float4* xp = reinterpret_cast<const float4*>(x + ((b * NS + s) * NE + h * 8));
    float4 x0 = xp[0];
    float4 x1 = xp[1];
    float4 t0 = reinterpret_cast<const float4*>(theta)[0];
    float4 t1 = reinterpret_cast<const float4*>(theta)[1];

    float c0 = cosf(x0.x + t0.x);
    float c1 = cosf(x0.y + t0.y);
    float c2 = cosf(x0.z + t0.z);
    float c3 = cosf(x0.w + t0.w);
    float c4 = cosf(x1.x + t1.x);
    float c5 = cosf(x1.y + t1.y);
    float c6 = cosf(x1.z + t1.z);
    float c7 = cosf(x1.w + t1.w);

    // meas[w] = c0*...*cw (w>=1), meas[0] = c1*...*c7
    float m1 = c0 * c1;
    float m2 = m1 * c2;
    float m3 = m2 * c3;
    float m4 = m3 * c4;
    float m5 = m4 * c5;
    float m6 = m5 * c6;
    float m7 = m6 * c7;
    float m0 = c1 * c2;
    m0 *= c3; m0 *= c4; m0 *= c5; m0 *= c6; m0 *= c7;

    // q pre-scaled: score = (q.k)/8; exp(score) = exp2( (q*QS).k )
    const float QS = 0.125f * 1.4426950408889634f;

    float4* qp = &g_qkv[((b * NH + h) * NS + s) * 2];
    qp[0] = make_float4(m0 * QS, m1 * QS, m2 * QS, m3);
    qp[1] = make_float4(m4, m5, m6, m7);
}

// ---------------------------------------------------------------------------
// Kernel 2: attention. One block = one (b,h) pair x one tile of 256 query rows.
// K/V for the whole sequence live in smem; inner loop is warp-uniform so
// every LDS is a broadcast (no bank conflicts). Scores in [-0.375,0.375]:
// plain exp (no max subtraction) is exact softmax up to normalization.
// ---------------------------------------------------------------------------
#define TILES 4
#define ATTN_THREADS 128

__global__ void __launch_bounds__(ATTN_THREADS) attn_kernel() {
    __shared__ float4 kv4[NS];   // (k0,k1,k2,v0)
    __shared__ float  v1s[NS];   // v1

    int bh   = blockIdx.x / TILES;
    int tile = blockIdx.x % TILES;
    const float4* base = &g_qkv[bh * NS * 2];

    for (int t = threadIdx.x; t < NS; t += ATTN_THREADS) {
        float4 f1 = base[2 * t];
        float4 f2 = base[2 * t + 1];
        kv4[t] = make_float4(f1.w, f2.x, f2.y, f2.z);
        v1s[t] = f2.w;
    }

    int row0 = tile * (NS / TILES) + threadIdx.x;   // 2 rows per thread
    int row1 = row0 + ATTN_THREADS;
    float4 qa = base[2 * row0];
    float4 qb = base[2 * row1];
    __syncthreads();

    float sum0 = 0.f, a00 = 0.f, a01 = 0.f;
    float sum1 = 0.f, a10 = 0.f, a11 = 0.f;

#pragma unroll 8
    for (int t = 0; t < NS; ++t) {
        float4 kv = kv4[t];
        float  v1 = v1s[t];
        float d0 = fmaf(qa.x, kv.x, fmaf(qa.y, kv.y, qa.z * kv.z));
        float d1 = fmaf(qb.x, kv.x, fmaf(qb.y, kv.y, qb.z * kv.z));
        float e0, e1;
        asm("ex2.approx.f32 %0, %1;" : "=f"(e0) : "f"(d0));
        asm("ex2.approx.f32 %0, %1;" : "=f"(e1) : "f"(d1));
        sum0 += e0; a00 = fmaf(e0, kv.w, a00); a01 = fmaf(e0, v1, a01);
        sum1 += e1; a10 = fmaf(e1, kv.w, a10); a11 = fmaf(e1, v1, a11);
    }

    int b = bh >> 3;
    int h = bh & 7;
    float inv0 = __fdividef(1.f, sum0);
    float inv1 = __fdividef(1.f, sum1);
    g_o16[(b * NS + row0) * 8 + h] = make_float2(a00 * inv0, a01 * inv0);
    g_o16[(b * NS + row1) * 8 + h] = make_float2(a10 * inv1, a11 * inv1);
}

// ---------------------------------------------------------------------------
// Kernel 3: combine. y[tok,e] = sum_f o16[tok,f]*W[e,f] + bias[e]
// W in smem padded to stride 17 (kills the 16-way bank conflict of stride 16).
// One block handles 32 tokens.
// ---------------------------------------------------------------------------
__global__ void __launch_bounds__(256) combine_kernel(const float* __restrict__ W,
                                                      const float* __restrict__ bias,
                                                      float* __restrict__ out) {
    __shared__ float Ws[64 * 17];
    __shared__ float bs[64];
    __shared__ float os[32 * 16];

    int tid = threadIdx.x;
    for (int i = tid; i < 64 * 16; i += 256)
        Ws[(i >> 4) * 17 + (i & 15)] = W[i];
    if (tid < 64) bs[tid] = bias[tid];

    int tokbase = blockIdx.x * 32;
    const float* o16 = reinterpret_cast<const float*>(g_o16);
    for (int i = tid; i < 32 * 16; i += 256)
        os[i] = o16[tokbase * 16 + i];
    __syncthreads();

    for (int idx = tid; idx < 32 * 64; idx += 256) {
        int tok = idx >> 6;
        int e   = idx & 63;
        float acc = bs[e];
        const float* wrow = &Ws[e * 17];
        const float* orow = &os[tok * 16];
#pragma unroll
        for (int f = 0; f < 16; ++f)
            acc = fmaf(orow[f], wrow[f], acc);
        out[(tokbase + tok) * 64 + e] = acc;
    }
}

// ---------------------------------------------------------------------------
extern "C" void kernel_launch(void* const* d_in, const int* in_sizes, int n_in,
                              void* d_out, int out_size) {
    const float* x     = (const float*)d_in[0];   // (8,1024,64)
    const float* theta = (const float*)d_in[1];   // (8,)
    const float* W     = (const float*)d_in[2];   // (64,16)
    const float* bias  = (const float*)d_in[3];   // (64,)
    float* out = (float*)d_out;                   // (8,1024,64)

    qkv_kernel<<<NB * NH * NS / 256, 256>>>(x, theta);
    attn_kernel<<<NB * NH * TILES, ATTN_THREADS>>>();
    combine_kernel<<<NB * NS / 32, 256>>>(W, bias, out);
}

// round 15
// speedup vs baseline: 1.0406x; 1.0008x over previous
#include <cuda_runtime.h>

#define NB 8
#define NH 8
#define NS 1024
#define NE 64

// Scratch (allocation-free rule: __device__ globals)
// layout: g_qkv[(b*NH+h)*NS + s] -> 2 float4: {q0',q1',q2',k0} {k1,k2,v0,v1}
// q' is pre-scaled by (1/8)*log2(e) so score exp becomes a single ex2.
__device__ float4 g_qkv[NB * NH * NS * 2];
// layout: g_o16[(b*NS+s)*8 + h] = (out0, out1) for head h
__device__ float2 g_o16[NB * NS * 8];

// ---------------------------------------------------------------------------
// Kernel 1: angles -> cosines -> prefix products -> q/k/v
// thread g: h fastest -> fully coalesced float4 reads of x
// ---------------------------------------------------------------------------
__global__ void __launch_bounds__(256) qkv_kernel(const float* __restrict__ x,
                                                  const float* __restrict__ theta) {
    int g = blockIdx.x * blockDim.x + threadIdx.x;   // 0..65535
    int h = g & 7;
    int s = (g >> 3) & (NS - 1);
    int b = g >> 13;

    const float4* xp = reinterpret_cast<const float4*>(x + ((b * NS + s) * NE + h * 8));
    float4 x0 = xp[0];
    float4 x1 = xp[1];
    float4 t0 = reinterpret_cast<const float4*>(theta)[0];
    float4 t1 = reinterpret_cast<const float4*>(theta)[1];

    float c0 = cosf(x0.x + t0.x);
    float c1 = cosf(x0.y + t0.y);
    float c2 = cosf(x0.z + t0.z);
    float c3 = cosf(x0.w + t0.w);
    float c4 = cosf(x1.x + t1.x);
    float c5 = cosf(x1.y + t1.y);
    float c6 = cosf(x1.z + t1.z);
    float c7 = cosf(x1.w + t1.w);

    // meas[w] = c0*...*cw (w>=1), meas[0] = c1*...*c7
    float m1 = c0 * c1;
    float m2 = m1 * c2;
    float m3 = m2 * c3;
    float m4 = m3 * c4;
    float m5 = m4 * c5;
    float m6 = m5 * c6;
    float m7 = m6 * c7;
    float m0 = c1 * c2;
    m0 *= c3; m0 *= c4; m0 *= c5; m0 *= c6; m0 *= c7;

    // q pre-scaled: score = (q.k)/8; exp(score) = exp2( (q*QS).k )
    const float QS = 0.125f * 1.4426950408889634f;

    float4* qp = &g_qkv[((b * NH + h) * NS + s) * 2];
    qp[0] = make_float4(m0 * QS, m1 * QS, m2 * QS, m3);
    qp[1] = make_float4(m4, m5, m6, m7);
}

// ---------------------------------------------------------------------------
// Kernel 2: attention. One block = one (b,h) pair x one tile of 256 query rows.
// K/V for the whole sequence live in smem; inner loop is warp-uniform so
// every LDS is a broadcast (no bank conflicts). Scores in [-0.375,0.375]:
// plain exp (no max subtraction) is exact softmax up to normalization.
// ---------------------------------------------------------------------------
#define TILES 4
#define ATTN_THREADS 128

__global__ void __launch_bounds__(ATTN_THREADS) attn_kernel() {
    __shared__ float4 kv4[NS];   // (k0,k1,k2,v0)
    __shared__ float  v1s[NS];   // v1

    int bh   = blockIdx.x / TILES;
    int tile = blockIdx.x % TILES;
    const float4* base = &g_qkv[bh * NS * 2];

    for (int t = threadIdx.x; t < NS; t += ATTN_THREADS) {
        float4 f1 = base[2 * t];
        float4 f2 = base[2 * t + 1];
        kv4[t] = make_float4(f1.w, f2.x, f2.y, f2.z);
        v1s[t] = f2.w;
    }

    int row0 = tile * (NS / TILES) + threadIdx.x;   // 2 rows per thread
    int row1 = row0 + ATTN_THREADS;
    float4 qa = base[2 * row0];
    float4 qb = base[2 * row1];
    __syncthreads();

    float sum0 = 0.f, a00 = 0.f, a01 = 0.f;
    float sum1 = 0.f, a10 = 0.f, a11 = 0.f;

#pragma unroll 8
    for (int t = 0; t < NS; ++t) {
        float4 kv = kv4[t];
        float  v1 = v1s[t];
        float d0 = fmaf(qa.x, kv.x, fmaf(qa.y, kv.y, qa.z * kv.z));
        float d1 = fmaf(qb.x, kv.x, fmaf(qb.y, kv.y, qb.z * kv.z));
        float e0, e1;
        asm("ex2.approx.f32 %0, %1;" : "=f"(e0) : "f"(d0));
        asm("ex2.approx.f32 %0, %1;" : "=f"(e1) : "f"(d1));
        sum0 += e0; a00 = fmaf(e0, kv.w, a00); a01 = fmaf(e0, v1, a01);
        sum1 += e1; a10 = fmaf(e1, kv.w, a10); a11 = fmaf(e1, v1, a11);
    }

    int b = bh >> 3;
    int h = bh & 7;
    float inv0 = __fdividef(1.f, sum0);
    float inv1 = __fdividef(1.f, sum1);
    g_o16[(b * NS + row0) * 8 + h] = make_float2(a00 * inv0, a01 * inv0);
    g_o16[(b * NS + row1) * 8 + h] = make_float2(a10 * inv1, a11 * inv1);
}

// ---------------------------------------------------------------------------
// Kernel 3: combine. y[tok,e] = sum_f o16[tok,f]*W[e,f] + bias[e]
// W in smem padded to stride 17 (kills the 16-way bank conflict of stride 16).
// One block handles 32 tokens.
// ---------------------------------------------------------------------------
__global__ void __launch_bounds__(256) combine_kernel(const float* __restrict__ W,
                                                      const float* __restrict__ bias,
                                                      float* __restrict__ out) {
    __shared__ float Ws[64 * 17];
    __shared__ float bs[64];
    __shared__ float os[32 * 16];

    int tid = threadIdx.x;
    for (int i = tid; i < 64 * 16; i += 256)
        Ws[(i >> 4) * 17 + (i & 15)] = W[i];
    if (tid < 64) bs[tid] = bias[tid];

    int tokbase = blockIdx.x * 32;
    const float* o16 = reinterpret_cast<const float*>(g_o16);
    for (int i = tid; i < 32 * 16; i += 256)
        os[i] = o16[tokbase * 16 + i];
    __syncthreads();

    for (int idx = tid; idx < 32 * 64; idx += 256) {
        int tok = idx >> 6;
        int e   = idx & 63;
        float acc = bs[e];
        const float* wrow = &Ws[e * 17];
        const float* orow = &os[tok * 16];
#pragma unroll
        for (int f = 0; f < 16; ++f)
            acc = fmaf(orow[f], wrow[f], acc);
        out[(tokbase + tok) * 64 + e] = acc;
    }
}

// ---------------------------------------------------------------------------
extern "C" void kernel_launch(void* const* d_in, const int* in_sizes, int n_in,
                              void* d_out, int out_size) {
    const float* x     = (const float*)d_in[0];   // (8,1024,64)
    const float* theta = (const float*)d_in[1];   // (8,)
    const float* W     = (const float*)d_in[2];   // (64,16)
    const float* bias  = (const float*)d_in[3];   // (64,)
    float* out = (float*)d_out;                   // (8,1024,64)

    qkv_kernel<<<NB * NH * NS / 256, 256>>>(x, theta);
    attn_kernel<<<NB * NH * TILES, ATTN_THREADS>>>();
    combine_kernel<<<NB * NS / 32, 256>>>(W, bias, out);
}